// round 5
// baseline (speedup 1.0000x reference)
#include <cuda_runtime.h>
#include <cuda_bf16.h>
#include <cstdint>

// ---------------------------------------------------------------------------
// Problem constants
// ---------------------------------------------------------------------------
#define BATCH   32
#define NAGENT  64
#define BN      2048
#define CIN0    16
#define HW0     30
#define FLAT    7744
#define EDIM    128
#define ADIM    5

// Conv smem ping-pong layout (floats)
#define SM_TOTAL   34176
#define OFF_IN0    0
#define OFF_OUT0   21632
#define OFF_OUT1   0
#define OFF_OUT2   24960
#define OFF_OUT3   0

#define CONV_THREADS 448

// ---------------------------------------------------------------------------
// Scratch
// ---------------------------------------------------------------------------
__device__ float g_flat [ (size_t)BN * FLAT ];
__device__ float g_acc0 [ BN * EDIM ];
__device__ float g_h    [ BN * EDIM ];

// ---------------------------------------------------------------------------
// f32x2 packed-math helpers
// ---------------------------------------------------------------------------
typedef unsigned long long u64;

__device__ __forceinline__ u64 pk2(float lo, float hi) {
    u64 r; asm("mov.b64 %0, {%1, %2};" : "=l"(r) : "f"(lo), "f"(hi)); return r;
}
__device__ __forceinline__ u64 pk1(float v) {
    u64 r; asm("mov.b64 %0, {%1, %1};" : "=l"(r) : "f"(v)); return r;
}
__device__ __forceinline__ u64 ffma2(u64 a, u64 b, u64 c) {
    u64 d; asm("fma.rn.f32x2 %0, %1, %2, %3;" : "=l"(d) : "l"(a), "l"(b), "l"(c));
    return d;
}
__device__ __forceinline__ void upk2(u64 v, float& lo, float& hi) {
    asm("mov.b64 {%0, %1}, %2;" : "=f"(lo), "=f"(hi) : "l"(v));
}

// ---------------------------------------------------------------------------
// Conv stage: 2 output channels x half-row per work item (low regs, many items)
// ---------------------------------------------------------------------------
template<int CI, int CO, int IHW, int OHW>
__device__ __forceinline__ void conv_stage2h(const float* __restrict__ in,
                                             float* __restrict__ out,
                                             const float* __restrict__ w,
                                             const float* __restrict__ bias,
                                             int tid, int nthr)
{
    constexpr int HALF  = OHW / 2;
    constexpr int ITEMS = (CO / 2) * OHW * 2;

    for (int p = tid; p < ITEMS; p += nthr) {
        int co2 = p / (OHW * 2);
        int rem = p - co2 * (OHW * 2);
        int y   = rem >> 1;
        int x0  = (rem & 1) * HALF;
        int co  = co2 * 2;

        u64 acc[HALF];
        u64 binit = pk2(__ldg(&bias[co]), __ldg(&bias[co + 1]));
        #pragma unroll
        for (int x = 0; x < HALF; x++) acc[x] = binit;

        const float* wA = w + (size_t)co * CI * 9;
        const float* wB = wA + (size_t)CI * 9;

        for (int ci = 0; ci < CI; ci++) {
            #pragma unroll
            for (int ky = 0; ky < 3; ky++) {
                const float* wa = wA + ci * 9 + ky * 3;
                const float* wb = wB + ci * 9 + ky * 3;
                u64 W0 = pk2(__ldg(&wa[0]), __ldg(&wb[0]));
                u64 W1 = pk2(__ldg(&wa[1]), __ldg(&wb[1]));
                u64 W2 = pk2(__ldg(&wa[2]), __ldg(&wb[2]));
                const float* r = in + (ci * IHW + y + ky) * IHW + x0;
                u64 b0 = pk1(r[0]);
                u64 b1 = pk1(r[1]);
                #pragma unroll
                for (int x = 0; x < HALF; x++) {
                    u64 b2 = pk1(r[x + 2]);
                    acc[x] = ffma2(b0, W0, acc[x]);
                    acc[x] = ffma2(b1, W1, acc[x]);
                    acc[x] = ffma2(b2, W2, acc[x]);
                    b0 = b1; b1 = b2;
                }
            }
        }
        float* oA = out + (co * OHW + y) * OHW + x0;
        float* oB = out + ((co + 1) * OHW + y) * OHW + x0;
        #pragma unroll
        for (int x = 0; x < HALF; x++) {
            float lo, hi; upk2(acc[x], lo, hi);
            oA[x] = fmaxf(lo, 0.0f);
            oB[x] = fmaxf(hi, 0.0f);
        }
    }
}

__global__ __launch_bounds__(CONV_THREADS, 1)
void conv_fused_kernel(const float* __restrict__ states,
                       const float* __restrict__ cw0, const float* __restrict__ cb0,
                       const float* __restrict__ cw1, const float* __restrict__ cb1,
                       const float* __restrict__ cw2, const float* __restrict__ cb2,
                       const float* __restrict__ cw3, const float* __restrict__ cb3,
                       float* __restrict__ flat)
{
    extern __shared__ float s[];
    const int agent = blockIdx.x;
    const int tid = threadIdx.x, nthr = blockDim.x;

    {
        const float4* src = (const float4*)(states + (size_t)agent * (CIN0*HW0*HW0));
        float4* dst = (float4*)(s + OFF_IN0);
        for (int i = tid; i < (CIN0*HW0*HW0)/4; i += nthr) dst[i] = src[i];
    }
    __syncthreads();
    conv_stage2h<16,16,30,28>(s + OFF_IN0 , s + OFF_OUT0, cw0, cb0, tid, nthr);
    __syncthreads();
    conv_stage2h<16,32,28,26>(s + OFF_OUT0, s + OFF_OUT1, cw1, cb1, tid, nthr);
    __syncthreads();
    conv_stage2h<32,16,26,24>(s + OFF_OUT1, s + OFF_OUT2, cw2, cb2, tid, nthr);
    __syncthreads();
    conv_stage2h<16,16,24,22>(s + OFF_OUT2, s + OFF_OUT3, cw3, cb3, tid, nthr);
    __syncthreads();
    {
        float4* fo = (float4*)(flat + (size_t)agent * FLAT);
        const float4* fs = (const float4*)(s + OFF_OUT3);
        for (int i = tid; i < FLAT/4; i += nthr) fo[i] = fs[i];
    }
}

// ---------------------------------------------------------------------------
// MLP0 split-K (unchanged)
// ---------------------------------------------------------------------------
#define KSPLIT  8
#define KCHUNK  968

__global__ void mlp0_splitk_kernel(const float* __restrict__ A,
                                   const float* __restrict__ W,
                                   float* __restrict__ Cacc)
{
    __shared__ float As[8 * 68];
    __shared__ float Ws[8 * 128];
    const int t  = threadIdx.x;
    const int kz = blockIdx.x;
    const int m0 = blockIdx.y * 64;
    const int kstart = kz * KCHUNK;
    const int tx = t & 31, ty = t >> 5;

    u64 acc[8][2];
    #pragma unroll
    for (int r = 0; r < 8; r++) { acc[r][0] = 0ull; acc[r][1] = 0ull; }

    for (int kk = 0; kk < KCHUNK; kk += 8) {
        __syncthreads();
        {
            int e = t * 2;
            int m = e >> 3, k = e & 7;
            const float* ap = A + (size_t)(m0 + m) * FLAT + kstart + kk + k;
            As[ k      * 68 + m] = ap[0];
            As[(k + 1) * 68 + m] = ap[1];
        }
        {
            int e = t * 4;
            int k = e >> 7, col = e & 127;
            *(float4*)&Ws[k * 128 + col] =
                *(const float4*)&W[(size_t)(kstart + kk + k) * EDIM + col];
        }
        __syncthreads();
        #pragma unroll
        for (int k = 0; k < 8; k++) {
            u64 B0 = *(const u64*)&Ws[k * 128 + tx * 4];
            u64 B1 = *(const u64*)&Ws[k * 128 + tx * 4 + 2];
            float4 a0 = *(float4*)&As[k * 68 + ty * 8];
            float4 a1 = *(float4*)&As[k * 68 + ty * 8 + 4];
            float av[8] = {a0.x,a0.y,a0.z,a0.w,a1.x,a1.y,a1.z,a1.w};
            #pragma unroll
            for (int r = 0; r < 8; r++) {
                u64 ar = pk1(av[r]);
                acc[r][0] = ffma2(ar, B0, acc[r][0]);
                acc[r][1] = ffma2(ar, B1, acc[r][1]);
            }
        }
    }
    #pragma unroll
    for (int r = 0; r < 8; r++) {
        int m = m0 + ty * 8 + r;
        float v0, v1, v2, v3;
        upk2(acc[r][0], v0, v1);
        upk2(acc[r][1], v2, v3);
        atomicAdd(&Cacc[(size_t)m * EDIM + tx * 4 + 0], v0);
        atomicAdd(&Cacc[(size_t)m * EDIM + tx * 4 + 1], v1);
        atomicAdd(&Cacc[(size_t)m * EDIM + tx * 4 + 2], v2);
        atomicAdd(&Cacc[(size_t)m * EDIM + tx * 4 + 3], v3);
    }
}

// ---------------------------------------------------------------------------
// 32-row x 128 GEMM helper (256 threads): each thread 4 rows x 4 cols
// ---------------------------------------------------------------------------
__device__ __forceinline__ void gemm32(const float* __restrict__ sIn,
                                       float* __restrict__ sOut,
                                       float* __restrict__ sW,
                                       const float* __restrict__ W,
                                       const float* __restrict__ bias,
                                       int relu, int t)
{
    __syncthreads();
    for (int i = t * 4; i < 128 * 128; i += 1024)
        *(float4*)&sW[i] = *(const float4*)&W[i];
    __syncthreads();

    const int tx = t & 31;
    const int ry = (t >> 5) * 4;
    u64 acc[4][2];
    u64 b0i = bias ? pk2(bias[tx*4+0], bias[tx*4+1]) : 0ull;
    u64 b1i = bias ? pk2(bias[tx*4+2], bias[tx*4+3]) : 0ull;
    #pragma unroll
    for (int r = 0; r < 4; r++) { acc[r][0] = b0i; acc[r][1] = b1i; }

    #pragma unroll 4
    for (int k = 0; k < 128; k++) {
        u64 B0 = *(const u64*)&sW[k * 128 + tx * 4];
        u64 B1 = *(const u64*)&sW[k * 128 + tx * 4 + 2];
        #pragma unroll
        for (int r = 0; r < 4; r++) {
            u64 ar = pk1(sIn[(ry + r) * 128 + k]);
            acc[r][0] = ffma2(ar, B0, acc[r][0]);
            acc[r][1] = ffma2(ar, B1, acc[r][1]);
        }
    }
    #pragma unroll
    for (int r = 0; r < 4; r++) {
        float v[4];
        upk2(acc[r][0], v[0], v[1]);
        upk2(acc[r][1], v[2], v[3]);
        #pragma unroll
        for (int c = 0; c < 4; c++)
            if (relu) v[c] = fmaxf(v[c], 0.0f);
        *(float4*)&sOut[(ry + r) * 128 + tx * 4] = *(float4*)v;
    }
}

// ---------------------------------------------------------------------------
// K1: pre-GCN chain, grid = 64, 32-row tiles (unchanged from round 4)
// ---------------------------------------------------------------------------
__global__ __launch_bounds__(256, 1)
void pre_gcn_kernel(const float* __restrict__ acc0,
                    const float* __restrict__ mb0,
                    const float* __restrict__ mw1, const float* __restrict__ mb1,
                    const float* __restrict__ mw2, const float* __restrict__ mb2,
                    const float* __restrict__ gw,
                    float* __restrict__ h)
{
    extern __shared__ float s[];
    float* sA = s;             // 32*128
    float* sB = s + 4096;      // 32*128
    float* sW = s + 8192;      // 128*128
    const int t = threadIdx.x;
    const size_t base = (size_t)blockIdx.x * 32 * EDIM;

    for (int i = t; i < 4096; i += 256) {
        int k = i & 127;
        sA[i] = fmaxf(acc0[base + i] + mb0[k], 0.0f);
    }

    gemm32(sA, sB, sW, mw1, mb1, 1, t);
    gemm32(sB, sA, sW, mw2, mb2, 0, t);
    gemm32(sA, sB, sW, gw,  nullptr, 0, t);

    __syncthreads();
    for (int i = t; i < 4096; i += 256) h[base + i] = sB[i];
}

// ---------------------------------------------------------------------------
// K2: GCN aggregation + DQN head, grid = (32 batches, 2 halves of 32 agents)
// smem: sH[64*128], sX[32*128], sY[32*128], sW[128*128 | adj+dis]
// ---------------------------------------------------------------------------
__global__ __launch_bounds__(256, 1)
void gcn_tail_kernel(const float* __restrict__ h,
                     const float* __restrict__ gb,
                     const float* __restrict__ fw0, const float* __restrict__ fb0,
                     const float* __restrict__ fw1, const float* __restrict__ fb1,
                     const float* __restrict__ fw2, const float* __restrict__ fb2,
                     const float* __restrict__ adj,
                     const int* __restrict__ inact,
                     float* __restrict__ out)
{
    extern __shared__ float s[];
    float* sH = s;            // 64*128  full h for this batch
    float* sX = s + 8192;     // 32*128
    float* sY = s + 12288;    // 32*128
    float* sW = s + 16384;    // 128*128; adj(4096)+dis(64) scratch
    const int b = blockIdx.x, t = threadIdx.x;
    const int j0 = blockIdx.y * 32;
    const size_t row0 = (size_t)b * NAGENT;

    for (int i = t; i < 8192; i += 256) sH[i] = h[row0 * EDIM + i];
    for (int i = t; i < 4096; i += 256) sW[i] = adj[(size_t)b * 4096 + i];
    __syncthreads();
    if (t < 64) {
        float d = 0.f;
        for (int i = 0; i < 64; i++) d += sW[i * 64 + t];
        sW[4096 + t] = (d > 0.f) ? rsqrtf(fmaxf(d, 1e-30f)) : 0.f;
    }
    __syncthreads();
    for (int i = t; i < 4096; i += 256) {
        int r = i >> 6, c = i & 63;
        sW[i] *= sW[4096 + r] * sW[4096 + c];
    }
    __syncthreads();
    // emb slice: rows j0..j0+31
    for (int o = t; o < 4096; o += 256) {
        int jl = o >> 7, d = o & 127;
        int j = j0 + jl;
        float a = gb[d];
        #pragma unroll 8
        for (int i = 0; i < 64; i++)
            a = fmaf(sW[i * 64 + j], sH[i * 128 + d], a);
        sX[o] = a;
    }

    gemm32(sX, sY, sW, fw0, fb0, 1, t);   // q1
    gemm32(sY, sX, sW, fw1, fb1, 1, t);   // q2

    __syncthreads();
    for (int p = t; p < 32 * ADIM; p += 256) {
        int row = p / ADIM, a = p - row * ADIM;
        float acc = fb2[a];
        #pragma unroll 8
        for (int k = 0; k < EDIM; k++)
            acc = fmaf(sX[row * 128 + k], __ldg(&fw2[k * ADIM + a]), acc);
        size_t grow = row0 + j0 + row;
        bool z = (inact[grow] != 0);
        out[grow * ADIM + a] = z ? 0.f : acc;
    }
}

__global__ void zero_kernel(float* __restrict__ p, int n)
{
    int i = blockIdx.x * blockDim.x + threadIdx.x;
    if (i < n) p[i] = 0.f;
}

// ---------------------------------------------------------------------------
// Launch
// ---------------------------------------------------------------------------
extern "C" void kernel_launch(void* const* d_in, const int* in_sizes, int n_in,
                              void* d_out, int out_size)
{
    (void)in_sizes; (void)n_in; (void)out_size;
    const float* states = (const float*)d_in[0];
    const float* adj    = (const float*)d_in[1];
    const int*   inact  = (const int*)d_in[2];
    const float* cw0 = (const float*)d_in[3];  const float* cb0 = (const float*)d_in[4];
    const float* cw1 = (const float*)d_in[5];  const float* cb1 = (const float*)d_in[6];
    const float* cw2 = (const float*)d_in[7];  const float* cb2 = (const float*)d_in[8];
    const float* cw3 = (const float*)d_in[9];  const float* cb3 = (const float*)d_in[10];
    const float* mw0 = (const float*)d_in[11]; const float* mb0 = (const float*)d_in[12];
    const float* mw1 = (const float*)d_in[13]; const float* mb1 = (const float*)d_in[14];
    const float* mw2 = (const float*)d_in[15]; const float* mb2 = (const float*)d_in[16];
    const float* gw  = (const float*)d_in[17]; const float* gb  = (const float*)d_in[18];
    const float* fw0 = (const float*)d_in[19]; const float* fb0 = (const float*)d_in[20];
    const float* fw1 = (const float*)d_in[21]; const float* fb1 = (const float*)d_in[22];
    const float* fw2 = (const float*)d_in[23]; const float* fb2 = (const float*)d_in[24];
    float* out = (float*)d_out;

    float *p_flat, *p_acc0, *p_h;
    cudaGetSymbolAddress((void**)&p_flat, g_flat);
    cudaGetSymbolAddress((void**)&p_acc0, g_acc0);
    cudaGetSymbolAddress((void**)&p_h,    g_h);

    const int convSmem = SM_TOTAL * 4;                          // 136704 B
    const int preSmem  = (4096 + 4096 + 16384) * 4;             //  98304 B
    const int tailSmem = (8192 + 4096 + 4096 + 16384) * 4;      // 131072 B
    cudaFuncSetAttribute(conv_fused_kernel, cudaFuncAttributeMaxDynamicSharedMemorySize, convSmem);
    cudaFuncSetAttribute(pre_gcn_kernel,    cudaFuncAttributeMaxDynamicSharedMemorySize, preSmem);
    cudaFuncSetAttribute(gcn_tail_kernel,   cudaFuncAttributeMaxDynamicSharedMemorySize, tailSmem);

    zero_kernel<<<(BN*EDIM + 255)/256, 256>>>(p_acc0, BN*EDIM);

    conv_fused_kernel<<<BN, CONV_THREADS, convSmem>>>(states, cw0, cb0, cw1, cb1,
                                                      cw2, cb2, cw3, cb3, p_flat);

    mlp0_splitk_kernel<<<dim3(KSPLIT, BN/64), 256>>>(p_flat, mw0, p_acc0);

    pre_gcn_kernel<<<BN/32, 256, preSmem>>>(p_acc0, mb0, mw1, mb1, mw2, mb2, gw, p_h);

    gcn_tail_kernel<<<dim3(BATCH, 2), 256, tailSmem>>>(p_h, gb, fw0, fb0, fw1, fb1,
                                                       fw2, fb2, adj, inact, out);
}

// round 6
// speedup vs baseline: 1.2265x; 1.2265x over previous
#include <cuda_runtime.h>
#include <cuda_bf16.h>
#include <cstdint>

// ---------------------------------------------------------------------------
// Problem constants
// ---------------------------------------------------------------------------
#define BATCH   32
#define NAGENT  64
#define BN      2048
#define CIN0    16
#define HW0     30
#define FLAT    7744
#define EDIM    128
#define ADIM    5

// Conv smem ping-pong layout (floats)
#define SM_TOTAL   34176
#define OFF_IN0    0
#define OFF_OUT0   21632
#define OFF_OUT1   0
#define OFF_OUT2   24960
#define OFF_OUT3   0

// Packed-weight smem region (u64 units), appended after float region
#define WPK0   0                 // 8*16*9  = 1152
#define WPK1   1152              // 16*16*9 = 2304
#define WPK2   3456              // 8*32*9  = 2304
#define WPK3   5760              // 8*16*9  = 1152
#define WPK_TOTAL 6912           // u64s -> 55296 bytes

#define CONV_THREADS 224

// ---------------------------------------------------------------------------
// Scratch
// ---------------------------------------------------------------------------
__device__ float g_flat [ (size_t)BN * FLAT ];
__device__ float g_acc0 [ BN * EDIM ];
__device__ float g_h    [ BN * EDIM ];

// ---------------------------------------------------------------------------
// f32x2 packed-math helpers
// ---------------------------------------------------------------------------
typedef unsigned long long u64;

__device__ __forceinline__ u64 pk2(float lo, float hi) {
    u64 r; asm("mov.b64 %0, {%1, %2};" : "=l"(r) : "f"(lo), "f"(hi)); return r;
}
__device__ __forceinline__ u64 pk1(float v) {
    u64 r; asm("mov.b64 %0, {%1, %1};" : "=l"(r) : "f"(v)); return r;
}
__device__ __forceinline__ u64 ffma2(u64 a, u64 b, u64 c) {
    u64 d; asm("fma.rn.f32x2 %0, %1, %2, %3;" : "=l"(d) : "l"(a), "l"(b), "l"(c));
    return d;
}
__device__ __forceinline__ void upk2(u64 v, float& lo, float& hi) {
    asm("mov.b64 {%0, %1}, %2;" : "=f"(lo), "=f"(hi) : "l"(v));
}

// ---------------------------------------------------------------------------
// Cooperative weight packing: w[CO][CI][3][3] -> wpk[(CO/2)][CI*9] u64 pairs
// ---------------------------------------------------------------------------
template<int CI, int CO>
__device__ __forceinline__ void pack_w(u64* __restrict__ dst,
                                       const float* __restrict__ w,
                                       int tid, int nthr)
{
    constexpr int PER = CI * 9;
    constexpr int N   = (CO / 2) * PER;
    for (int i = tid; i < N; i += nthr) {
        int pair = i / PER;
        int r    = i - pair * PER;
        dst[i] = pk2(__ldg(&w[(2 * pair    ) * PER + r]),
                     __ldg(&w[(2 * pair + 1) * PER + r]));
    }
}

// ---------------------------------------------------------------------------
// Conv stage: 2 output channels x full row per work item, weights from smem
// ---------------------------------------------------------------------------
template<int CI, int CO, int IHW, int OHW>
__device__ __forceinline__ void conv_stage2(const float* __restrict__ in,
                                            float* __restrict__ out,
                                            const u64* __restrict__ wpk,
                                            const float* __restrict__ bias,
                                            int tid, int nthr)
{
    constexpr int ITEMS = (CO / 2) * OHW;
    for (int p = tid; p < ITEMS; p += nthr) {
        int co2 = p / OHW;
        int y   = p - co2 * OHW;

        u64 acc[OHW];
        u64 binit = pk2(__ldg(&bias[2 * co2]), __ldg(&bias[2 * co2 + 1]));
        #pragma unroll
        for (int x = 0; x < OHW; x++) acc[x] = binit;

        const u64* wp0 = wpk + co2 * (CI * 9);

        for (int ci = 0; ci < CI; ci++) {
            #pragma unroll
            for (int ky = 0; ky < 3; ky++) {
                const u64* wp = wp0 + ci * 9 + ky * 3;
                u64 W0 = wp[0];
                u64 W1 = wp[1];
                u64 W2 = wp[2];
                const float* r = in + (ci * IHW + y + ky) * IHW;
                u64 b0 = pk1(r[0]);
                u64 b1 = pk1(r[1]);
                #pragma unroll
                for (int x = 0; x < OHW; x++) {
                    u64 b2 = pk1(r[x + 2]);
                    acc[x] = ffma2(b0, W0, acc[x]);
                    acc[x] = ffma2(b1, W1, acc[x]);
                    acc[x] = ffma2(b2, W2, acc[x]);
                    b0 = b1; b1 = b2;
                }
            }
        }
        float* oA = out + (2 * co2 * OHW + y) * OHW;
        float* oB = out + ((2 * co2 + 1) * OHW + y) * OHW;
        #pragma unroll
        for (int x = 0; x < OHW; x++) {
            float lo, hi; upk2(acc[x], lo, hi);
            oA[x] = fmaxf(lo, 0.0f);
            oB[x] = fmaxf(hi, 0.0f);
        }
    }
}

__global__ __launch_bounds__(CONV_THREADS, 1)
void conv_fused_kernel(const float* __restrict__ states,
                       const float* __restrict__ cw0, const float* __restrict__ cb0,
                       const float* __restrict__ cw1, const float* __restrict__ cb1,
                       const float* __restrict__ cw2, const float* __restrict__ cb2,
                       const float* __restrict__ cw3, const float* __restrict__ cb3,
                       float* __restrict__ flat)
{
    extern __shared__ float s[];
    u64* wpk = (u64*)(s + SM_TOTAL);
    const int agent = blockIdx.x;
    const int tid = threadIdx.x, nthr = blockDim.x;

    // pack all conv weights into smem (u64 channel-pairs)
    pack_w<16,16>(wpk + WPK0, cw0, tid, nthr);
    pack_w<16,32>(wpk + WPK1, cw1, tid, nthr);
    pack_w<32,16>(wpk + WPK2, cw2, tid, nthr);
    pack_w<16,16>(wpk + WPK3, cw3, tid, nthr);

    // load input image [16,30,30]
    {
        const float4* src = (const float4*)(states + (size_t)agent * (CIN0*HW0*HW0));
        float4* dst = (float4*)(s + OFF_IN0);
        for (int i = tid; i < (CIN0*HW0*HW0)/4; i += nthr) dst[i] = src[i];
    }
    __syncthreads();
    conv_stage2<16,16,30,28>(s + OFF_IN0 , s + OFF_OUT0, wpk + WPK0, cb0, tid, nthr);
    __syncthreads();
    conv_stage2<16,32,28,26>(s + OFF_OUT0, s + OFF_OUT1, wpk + WPK1, cb1, tid, nthr);
    __syncthreads();
    conv_stage2<32,16,26,24>(s + OFF_OUT1, s + OFF_OUT2, wpk + WPK2, cb2, tid, nthr);
    __syncthreads();
    conv_stage2<16,16,24,22>(s + OFF_OUT2, s + OFF_OUT3, wpk + WPK3, cb3, tid, nthr);
    __syncthreads();
    {
        float4* fo = (float4*)(flat + (size_t)agent * FLAT);
        const float4* fs = (const float4*)(s + OFF_OUT3);
        for (int i = tid; i < FLAT/4; i += nthr) fo[i] = fs[i];
    }
}

// ---------------------------------------------------------------------------
// MLP0 split-K (unchanged)
// ---------------------------------------------------------------------------
#define KSPLIT  8
#define KCHUNK  968

__global__ void mlp0_splitk_kernel(const float* __restrict__ A,
                                   const float* __restrict__ W,
                                   float* __restrict__ Cacc)
{
    __shared__ float As[8 * 68];
    __shared__ float Ws[8 * 128];
    const int t  = threadIdx.x;
    const int kz = blockIdx.x;
    const int m0 = blockIdx.y * 64;
    const int kstart = kz * KCHUNK;
    const int tx = t & 31, ty = t >> 5;

    u64 acc[8][2];
    #pragma unroll
    for (int r = 0; r < 8; r++) { acc[r][0] = 0ull; acc[r][1] = 0ull; }

    for (int kk = 0; kk < KCHUNK; kk += 8) {
        __syncthreads();
        {
            int e = t * 2;
            int m = e >> 3, k = e & 7;
            const float* ap = A + (size_t)(m0 + m) * FLAT + kstart + kk + k;
            As[ k      * 68 + m] = ap[0];
            As[(k + 1) * 68 + m] = ap[1];
        }
        {
            int e = t * 4;
            int k = e >> 7, col = e & 127;
            *(float4*)&Ws[k * 128 + col] =
                *(const float4*)&W[(size_t)(kstart + kk + k) * EDIM + col];
        }
        __syncthreads();
        #pragma unroll
        for (int k = 0; k < 8; k++) {
            u64 B0 = *(const u64*)&Ws[k * 128 + tx * 4];
            u64 B1 = *(const u64*)&Ws[k * 128 + tx * 4 + 2];
            float4 a0 = *(float4*)&As[k * 68 + ty * 8];
            float4 a1 = *(float4*)&As[k * 68 + ty * 8 + 4];
            float av[8] = {a0.x,a0.y,a0.z,a0.w,a1.x,a1.y,a1.z,a1.w};
            #pragma unroll
            for (int r = 0; r < 8; r++) {
                u64 ar = pk1(av[r]);
                acc[r][0] = ffma2(ar, B0, acc[r][0]);
                acc[r][1] = ffma2(ar, B1, acc[r][1]);
            }
        }
    }
    #pragma unroll
    for (int r = 0; r < 8; r++) {
        int m = m0 + ty * 8 + r;
        float v0, v1, v2, v3;
        upk2(acc[r][0], v0, v1);
        upk2(acc[r][1], v2, v3);
        atomicAdd(&Cacc[(size_t)m * EDIM + tx * 4 + 0], v0);
        atomicAdd(&Cacc[(size_t)m * EDIM + tx * 4 + 1], v1);
        atomicAdd(&Cacc[(size_t)m * EDIM + tx * 4 + 2], v2);
        atomicAdd(&Cacc[(size_t)m * EDIM + tx * 4 + 3], v3);
    }
}

// ---------------------------------------------------------------------------
// 32-row x 128 GEMM helper (256 threads): each thread 4 rows x 4 cols
// ---------------------------------------------------------------------------
__device__ __forceinline__ void gemm32(const float* __restrict__ sIn,
                                       float* __restrict__ sOut,
                                       float* __restrict__ sW,
                                       const float* __restrict__ W,
                                       const float* __restrict__ bias,
                                       int relu, int t)
{
    __syncthreads();
    for (int i = t * 4; i < 128 * 128; i += 1024)
        *(float4*)&sW[i] = *(const float4*)&W[i];
    __syncthreads();

    const int tx = t & 31;
    const int ry = (t >> 5) * 4;
    u64 acc[4][2];
    u64 b0i = bias ? pk2(bias[tx*4+0], bias[tx*4+1]) : 0ull;
    u64 b1i = bias ? pk2(bias[tx*4+2], bias[tx*4+3]) : 0ull;
    #pragma unroll
    for (int r = 0; r < 4; r++) { acc[r][0] = b0i; acc[r][1] = b1i; }

    #pragma unroll 4
    for (int k = 0; k < 128; k++) {
        u64 B0 = *(const u64*)&sW[k * 128 + tx * 4];
        u64 B1 = *(const u64*)&sW[k * 128 + tx * 4 + 2];
        #pragma unroll
        for (int r = 0; r < 4; r++) {
            u64 ar = pk1(sIn[(ry + r) * 128 + k]);
            acc[r][0] = ffma2(ar, B0, acc[r][0]);
            acc[r][1] = ffma2(ar, B1, acc[r][1]);
        }
    }
    #pragma unroll
    for (int r = 0; r < 4; r++) {
        float v[4];
        upk2(acc[r][0], v[0], v[1]);
        upk2(acc[r][1], v[2], v[3]);
        #pragma unroll
        for (int c = 0; c < 4; c++)
            if (relu) v[c] = fmaxf(v[c], 0.0f);
        *(float4*)&sOut[(ry + r) * 128 + tx * 4] = *(float4*)v;
    }
}

// ---------------------------------------------------------------------------
// K1: pre-GCN chain, grid = 64, 32-row tiles
// ---------------------------------------------------------------------------
__global__ __launch_bounds__(256, 1)
void pre_gcn_kernel(const float* __restrict__ acc0,
                    const float* __restrict__ mb0,
                    const float* __restrict__ mw1, const float* __restrict__ mb1,
                    const float* __restrict__ mw2, const float* __restrict__ mb2,
                    const float* __restrict__ gw,
                    float* __restrict__ h)
{
    extern __shared__ float s[];
    float* sA = s;             // 32*128
    float* sB = s + 4096;      // 32*128
    float* sW = s + 8192;      // 128*128
    const int t = threadIdx.x;
    const size_t base = (size_t)blockIdx.x * 32 * EDIM;

    for (int i = t; i < 4096; i += 256) {
        int k = i & 127;
        sA[i] = fmaxf(acc0[base + i] + mb0[k], 0.0f);
    }

    gemm32(sA, sB, sW, mw1, mb1, 1, t);
    gemm32(sB, sA, sW, mw2, mb2, 0, t);
    gemm32(sA, sB, sW, gw,  nullptr, 0, t);

    __syncthreads();
    for (int i = t; i < 4096; i += 256) h[base + i] = sB[i];
}

// ---------------------------------------------------------------------------
// K2: GCN aggregation + DQN head, grid = (32 batches, 2 halves of 32 agents)
// ---------------------------------------------------------------------------
__global__ __launch_bounds__(256, 1)
void gcn_tail_kernel(const float* __restrict__ h,
                     const float* __restrict__ gb,
                     const float* __restrict__ fw0, const float* __restrict__ fb0,
                     const float* __restrict__ fw1, const float* __restrict__ fb1,
                     const float* __restrict__ fw2, const float* __restrict__ fb2,
                     const float* __restrict__ adj,
                     const int* __restrict__ inact,
                     float* __restrict__ out)
{
    extern __shared__ float s[];
    float* sH = s;            // 64*128  full h for this batch
    float* sX = s + 8192;     // 32*128
    float* sY = s + 12288;    // 32*128
    float* sW = s + 16384;    // 128*128; adj(4096)+dis(64) scratch
    const int b = blockIdx.x, t = threadIdx.x;
    const int j0 = blockIdx.y * 32;
    const size_t row0 = (size_t)b * NAGENT;

    for (int i = t; i < 8192; i += 256) sH[i] = h[row0 * EDIM + i];
    for (int i = t; i < 4096; i += 256) sW[i] = adj[(size_t)b * 4096 + i];
    __syncthreads();
    if (t < 64) {
        float d = 0.f;
        for (int i = 0; i < 64; i++) d += sW[i * 64 + t];
        sW[4096 + t] = (d > 0.f) ? rsqrtf(fmaxf(d, 1e-30f)) : 0.f;
    }
    __syncthreads();
    for (int i = t; i < 4096; i += 256) {
        int r = i >> 6, c = i & 63;
        sW[i] *= sW[4096 + r] * sW[4096 + c];
    }
    __syncthreads();
    for (int o = t; o < 4096; o += 256) {
        int jl = o >> 7, d = o & 127;
        int j = j0 + jl;
        float a = gb[d];
        #pragma unroll 8
        for (int i = 0; i < 64; i++)
            a = fmaf(sW[i * 64 + j], sH[i * 128 + d], a);
        sX[o] = a;
    }

    gemm32(sX, sY, sW, fw0, fb0, 1, t);   // q1
    gemm32(sY, sX, sW, fw1, fb1, 1, t);   // q2

    __syncthreads();
    for (int p = t; p < 32 * ADIM; p += 256) {
        int row = p / ADIM, a = p - row * ADIM;
        float acc = fb2[a];
        #pragma unroll 8
        for (int k = 0; k < EDIM; k++)
            acc = fmaf(sX[row * 128 + k], __ldg(&fw2[k * ADIM + a]), acc);
        size_t grow = row0 + j0 + row;
        bool z = (inact[grow] != 0);
        out[grow * ADIM + a] = z ? 0.f : acc;
    }
}

__global__ void zero_kernel(float* __restrict__ p, int n)
{
    int i = blockIdx.x * blockDim.x + threadIdx.x;
    if (i < n) p[i] = 0.f;
}

// ---------------------------------------------------------------------------
// Launch
// ---------------------------------------------------------------------------
extern "C" void kernel_launch(void* const* d_in, const int* in_sizes, int n_in,
                              void* d_out, int out_size)
{
    (void)in_sizes; (void)n_in; (void)out_size;
    const float* states = (const float*)d_in[0];
    const float* adj    = (const float*)d_in[1];
    const int*   inact  = (const int*)d_in[2];
    const float* cw0 = (const float*)d_in[3];  const float* cb0 = (const float*)d_in[4];
    const float* cw1 = (const float*)d_in[5];  const float* cb1 = (const float*)d_in[6];
    const float* cw2 = (const float*)d_in[7];  const float* cb2 = (const float*)d_in[8];
    const float* cw3 = (const float*)d_in[9];  const float* cb3 = (const float*)d_in[10];
    const float* mw0 = (const float*)d_in[11]; const float* mb0 = (const float*)d_in[12];
    const float* mw1 = (const float*)d_in[13]; const float* mb1 = (const float*)d_in[14];
    const float* mw2 = (const float*)d_in[15]; const float* mb2 = (const float*)d_in[16];
    const float* gw  = (const float*)d_in[17]; const float* gb  = (const float*)d_in[18];
    const float* fw0 = (const float*)d_in[19]; const float* fb0 = (const float*)d_in[20];
    const float* fw1 = (const float*)d_in[21]; const float* fb1 = (const float*)d_in[22];
    const float* fw2 = (const float*)d_in[23]; const float* fb2 = (const float*)d_in[24];
    float* out = (float*)d_out;

    float *p_flat, *p_acc0, *p_h;
    cudaGetSymbolAddress((void**)&p_flat, g_flat);
    cudaGetSymbolAddress((void**)&p_acc0, g_acc0);
    cudaGetSymbolAddress((void**)&p_h,    g_h);

    const int convSmem = SM_TOTAL * 4 + WPK_TOTAL * 8;          // 192000 B
    const int preSmem  = (4096 + 4096 + 16384) * 4;             //  98304 B
    const int tailSmem = (8192 + 4096 + 4096 + 16384) * 4;      // 131072 B
    cudaFuncSetAttribute(conv_fused_kernel, cudaFuncAttributeMaxDynamicSharedMemorySize, convSmem);
    cudaFuncSetAttribute(pre_gcn_kernel,    cudaFuncAttributeMaxDynamicSharedMemorySize, preSmem);
    cudaFuncSetAttribute(gcn_tail_kernel,   cudaFuncAttributeMaxDynamicSharedMemorySize, tailSmem);

    zero_kernel<<<(BN*EDIM + 255)/256, 256>>>(p_acc0, BN*EDIM);

    conv_fused_kernel<<<BN, CONV_THREADS, convSmem>>>(states, cw0, cb0, cw1, cb1,
                                                      cw2, cb2, cw3, cb3, p_flat);

    mlp0_splitk_kernel<<<dim3(KSPLIT, BN/64), 256>>>(p_flat, mw0, p_acc0);

    pre_gcn_kernel<<<BN/32, 256, preSmem>>>(p_acc0, mb0, mw1, mb1, mw2, mb2, gw, p_h);

    gcn_tail_kernel<<<dim3(BATCH, 2), 256, tailSmem>>>(p_h, gb, fw0, fb0, fw1, fb1,
                                                       fw2, fb2, adj, inact, out);
}